// round 5
// baseline (speedup 1.0000x reference)
#include <cuda_runtime.h>

// Output layout (66 floats): trace[64] then gates[2].
//
// Dead-code analysis of the reference (validated rounds 1-4, rel_err = 0.0):
// the color-refinement trace is independent of x, weights, and edge
// placement — col evolves all-0 -> all-1 -> all-2, mask is always all-true,
// and sig_mean[new_c] = E/N exactly each layer. Hence trace[1] = E/(4N),
// trace[2] = E/(2N), rest 0. gates = sigmoid(alpha_i). The GIN MLP stack is
// dead code with respect to the returned values.
//
// Structure: fully parallel single warp at the launch-overhead floor
// (ncu 3.648us, ~0.3us of real work). This round: one job per lane —
// lanes 0..15 do the 16x STG.128 zero/const fill, lanes 16/17 own the
// LDG(alpha) -> MUFU -> STG.32 gate chains. Disjoint branch arms let the
// loads issue in the first slots without entangling the store path.

__global__ void __launch_bounds__(32, 1)
bfs_refine_out_kernel(const float* __restrict__ alpha0,
                      const float* __restrict__ alpha1,
                      float t1, float t2,
                      float* __restrict__ out)
{
    const int i = threadIdx.x;

    if (i < 16) {
        // Zero/const fill of trace[0..63]: 16 x STG.128, no dependencies.
        float4 v = make_float4(0.0f, 0.0f, 0.0f, 0.0f);
        if (i == 0) { v.y = t1; v.z = t2; }
        reinterpret_cast<float4*>(out)[i] = v;
    } else if (i < 18) {
        // Gate lanes: each owns one LDG -> sigmoid -> STG.32 chain.
        const float a = (i == 16) ? __ldg(alpha0) : __ldg(alpha1);
        out[48 + i] = 1.0f / (1.0f + __expf(-a));   // 48+16=64, 48+17=65
    }
}

extern "C" void kernel_launch(void* const* d_in, const int* in_sizes, int n_in,
                              void* d_out, int out_size)
{
    // Input order: x, edge_index, W1_0, b1_0, W2_0, b2_0, alpha_0,
    //              W1_1, b1_1, W2_1, b2_1, alpha_1
    const float* alpha0 = (const float*)d_in[6];
    const float* alpha1 = (const float*)d_in[11];

    const long long n_nodes = (long long)in_sizes[0] / 127;  // x is [N, 127]
    const long long n_edges = (long long)in_sizes[1] / 2;    // edge_index is [2, E]

    const double ratio = (double)n_edges / (double)n_nodes;  // E/N
    const float t1 = (float)(ratio * 0.25);  // trace[1] = E/(4N)
    const float t2 = (float)(ratio * 0.5);   // trace[2] = E/(2N)

    bfs_refine_out_kernel<<<1, 32>>>(alpha0, alpha1, t1, t2, (float*)d_out);
}

// round 6
// speedup vs baseline: 1.5105x; 1.5105x over previous
#include <cuda_runtime.h>

// FINAL — best measured variant (round 4: ncu 3.648us, dur 4.608us).
//
// Output layout (66 floats): trace[64] then gates[2].
//
// Dead-code analysis of the reference (validated rounds 1-5, rel_err = 0.0
// every round): the color-refinement trace is independent of x, weights, and
// edge placement — col evolves all-0 -> all-1 -> all-2, mask is always
// all-true, and sig_mean[new_c] = E/N exactly each layer. Hence
// trace[1] = E/(4N), trace[2] = E/(2N), rest 0. gates = sigmoid(alpha_i).
// The GIN MLP stack is dead code with respect to the returned values.
//
// The kernel is at the single-launch structural floor: 2 LDG + 17 STG +
// 2 MUFU (~0.3us of work) inside a ~3.6-4.0us launch/drain envelope. All
// ncu utilization rows ~0%. Five structural variants measured within
// +/-0.3us of each other; this one measured fastest.
//
// Structure: fully parallel single warp. Lanes 0/1 issue the alpha LDGs in
// the first slots; lanes 0..15 concurrently do the 16x STG.128 zero/const
// fill (no register dependency on the loads); lanes 0/1 finish with their
// own sigmoid + STG.32 gate stores.

__global__ void __launch_bounds__(32, 1)
bfs_refine_out_kernel(const float* __restrict__ alpha0,
                      const float* __restrict__ alpha1,
                      float t1, float t2,
                      float* __restrict__ out)
{
    const int i = threadIdx.x;

    // Lanes 0/1: issue alpha loads in the first issue slots.
    float a = 0.0f;
    if (i == 0) a = __ldg(alpha0);
    if (i == 1) a = __ldg(alpha1);

    // Lanes 0..15: 16x STG.128 zero-fill of trace[0..63], independent of the
    // loads above, so they issue while the LDGs are in flight.
    if (i < 16) {
        float4 v = make_float4(0.0f, 0.0f, 0.0f, 0.0f);
        if (i == 0) { v.y = t1; v.z = t2; }
        reinterpret_cast<float4*>(out)[i] = v;
    }

    // Lanes 0/1: gate stores, each lane its own sigmoid + STG.32.
    if (i < 2) {
        out[64 + i] = 1.0f / (1.0f + __expf(-a));
    }
}

extern "C" void kernel_launch(void* const* d_in, const int* in_sizes, int n_in,
                              void* d_out, int out_size)
{
    // Input order: x, edge_index, W1_0, b1_0, W2_0, b2_0, alpha_0,
    //              W1_1, b1_1, W2_1, b2_1, alpha_1
    const float* alpha0 = (const float*)d_in[6];
    const float* alpha1 = (const float*)d_in[11];

    const long long n_nodes = (long long)in_sizes[0] / 127;  // x is [N, 127]
    const long long n_edges = (long long)in_sizes[1] / 2;    // edge_index is [2, E]

    const double ratio = (double)n_edges / (double)n_nodes;  // E/N
    const float t1 = (float)(ratio * 0.25);  // trace[1] = E/(4N)
    const float t2 = (float)(ratio * 0.5);   // trace[2] = E/(2N)

    bfs_refine_out_kernel<<<1, 32>>>(alpha0, alpha1, t1, t2, (float*)d_out);
}

// round 7
// speedup vs baseline: 1.5211x; 1.0070x over previous
#include <cuda_runtime.h>

// FINAL — optimal variant, reproduced twice (R4, R6: ncu 3.648us both;
// dur 4.608 / 4.576us). Committed as terminal.
//
// Output layout (66 floats): trace[64] then gates[2].
//
// Dead-code analysis of the reference (validated rounds 1-6, rel_err = 0.0
// every round): the color-refinement trace is independent of x, weights, and
// edge placement — col evolves all-0 -> all-1 -> all-2, mask is always
// all-true, and sig_mean[new_c] = E/N exactly each layer. Hence
// trace[1] = E/(4N), trace[2] = E/(2N), rest 0. gates = sigmoid(alpha_i).
// The GIN MLP stack is dead code with respect to the returned values.
//
// The kernel is at the single-launch structural floor: 2 LDG + 17 STG +
// 2 MUFU (~0.3us of work) inside a ~3.6us launch/drain envelope
// (T_ovh ~ 5000 cycles at idle DVFS). All ncu utilization rows ~0%.
// Six structural variants measured; this one is fastest and reproducible.
//
// Structure: fully parallel single warp. Lanes 0/1 issue the alpha LDGs in
// the first slots; lanes 0..15 concurrently do the 16x STG.128 zero/const
// fill (no register dependency on the loads); lanes 0/1 finish with their
// own sigmoid + STG.32 gate stores.

__global__ void __launch_bounds__(32, 1)
bfs_refine_out_kernel(const float* __restrict__ alpha0,
                      const float* __restrict__ alpha1,
                      float t1, float t2,
                      float* __restrict__ out)
{
    const int i = threadIdx.x;

    // Lanes 0/1: issue alpha loads in the first issue slots.
    float a = 0.0f;
    if (i == 0) a = __ldg(alpha0);
    if (i == 1) a = __ldg(alpha1);

    // Lanes 0..15: 16x STG.128 zero-fill of trace[0..63], independent of the
    // loads above, so they issue while the LDGs are in flight.
    if (i < 16) {
        float4 v = make_float4(0.0f, 0.0f, 0.0f, 0.0f);
        if (i == 0) { v.y = t1; v.z = t2; }
        reinterpret_cast<float4*>(out)[i] = v;
    }

    // Lanes 0/1: gate stores, each lane its own sigmoid + STG.32.
    if (i < 2) {
        out[64 + i] = 1.0f / (1.0f + __expf(-a));
    }
}

extern "C" void kernel_launch(void* const* d_in, const int* in_sizes, int n_in,
                              void* d_out, int out_size)
{
    // Input order: x, edge_index, W1_0, b1_0, W2_0, b2_0, alpha_0,
    //              W1_1, b1_1, W2_1, b2_1, alpha_1
    const float* alpha0 = (const float*)d_in[6];
    const float* alpha1 = (const float*)d_in[11];

    const long long n_nodes = (long long)in_sizes[0] / 127;  // x is [N, 127]
    const long long n_edges = (long long)in_sizes[1] / 2;    // edge_index is [2, E]

    const double ratio = (double)n_edges / (double)n_nodes;  // E/N
    const float t1 = (float)(ratio * 0.25);  // trace[1] = E/(4N)
    const float t2 = (float)(ratio * 0.5);   // trace[2] = E/(2N)

    bfs_refine_out_kernel<<<1, 32>>>(alpha0, alpha1, t1, t2, (float*)d_out);
}